// round 13
// baseline (speedup 1.0000x reference)
#include <cuda_runtime.h>
#include <cuda_fp16.h>

#define NN   50000
#define EE   800000
#define INC  128
#define OUTC 32
#define HH   4
#define EDIM 16
#define HO   128          // H*OUT
#define ENF  (EE + NN)    // edges + self loops = 850000 (divisible by 16)
#define NBATCH (ENF / 16) // 53125 mma warp batches
#define SLOPE 0.2f

// fat-kernel block partition (striped by a coprime swizzle)
#define GEMM_NB 1563      // ceil(NN/32), 32 rows per block
#define DEG_NB  3125      // ceil(EE/256)
#define ZERO_NB 512
#define FAT_NB  (GEMM_NB + DEG_NB + ZERO_NB)   // 5200
#define FAT_SWZ 1997      // coprime with 5200

// ---------------- scratch (device globals; no allocation allowed) ----------
__device__ uint2    g_xlh[(size_t)NN * 32];      // x@W_l+b_l fp16 (12.8 MB)
__device__ uint2    g_xrh[(size_t)NN * 32];      // x@W_r+b_r fp16 (12.8 MB)
__device__ float    g_deg[NN];                   // in-degree
__device__ float    g_asum[(size_t)NN * EDIM];   // scatter-sum of edge attrs
__device__ float    g_denom[(size_t)NN * HH];    // softmax denominators
__device__ float4   g_accum[(size_t)NN * OUTC];  // sum exp(s)*x_l[src] (25.6 MB)

// ---------------- helpers --------------------------------------------------
__device__ __forceinline__ float lrelu(float v) { return fmaxf(v, SLOPE * v); }

__device__ __forceinline__ void red_add_v4(float4* addr, float4 v) {
    asm volatile("red.global.add.v4.f32 [%0], {%1,%2,%3,%4};"
                 :: "l"(addr), "f"(v.x), "f"(v.y), "f"(v.z), "f"(v.w)
                 : "memory");
}

// pack two f32 into f16x2: lo -> bits[15:0], hi -> bits[31:16]
__device__ __forceinline__ unsigned pack_h2(float hi, float lo) {
    unsigned r;
    asm("cvt.rn.f16x2.f32 %0, %1, %2;" : "=r"(r) : "f"(hi), "f"(lo));
    return r;
}

// packed fp32x2 FMA (Blackwell FFMA2 — only reachable via PTX)
__device__ __forceinline__ unsigned long long pk2(float lo, float hi) {
    unsigned long long r;
    asm("mov.b64 %0, {%1, %2};" : "=l"(r) : "f"(lo), "f"(hi));
    return r;
}
__device__ __forceinline__ void fma2(unsigned long long& d, unsigned long long a,
                                     unsigned long long b, unsigned long long c) {
    asm("fma.rn.f32x2 %0, %1, %2, %3;" : "=l"(d) : "l"(a), "l"(b), "l"(c));
}
__device__ __forceinline__ float2 upk2(unsigned long long v) {
    float2 f;
    asm("mov.b64 {%0, %1}, %2;" : "=f"(f.x), "=f"(f.y) : "l"(v));
    return f;
}

// ---------------- kernel 1: FAT prologue (striped block types) --------------
// gemm blocks: x@W_l / x@W_r (FFMA2), 32 rows/block, fp16 out
// deg blocks:  degree + attr scatter-sum
// zero blocks: zero accum + denom
// Types are striped across blockIdx via a coprime swizzle so FMA-bound,
// atomic-bound and DRAM-bound blocks co-reside on every SM from wave 1.
__global__ void __launch_bounds__(256, 3)
fat_prologue(const float* __restrict__ x,
             const float* __restrict__ Wl, const float* __restrict__ bl,
             const float* __restrict__ Wr, const float* __restrict__ br,
             const int* __restrict__ ei,
             const float* __restrict__ eattr) {
    __shared__ float xs[32][INC];
    int b = (int)(((long)blockIdx.x * FAT_SWZ) % FAT_NB);
    int tid = threadIdx.x;

    if (b < GEMM_NB) {
        // ---------------- GEMM part: 32 rows ----------------
        int row0 = b * 32;
        const float4* x4 = (const float4*)x;
        for (int i = tid; i < 32 * 32; i += 256) {
            int r = i >> 5, c = i & 31;
            float4 v = make_float4(0.f, 0.f, 0.f, 0.f);
            if (row0 + r < NN) v = x4[(long)(row0 + r) * 32 + c];
            ((float4*)xs[r])[c] = v;
        }
        __syncthreads();

        int tx = tid & 31, ty = tid >> 5;
        unsigned long long accL[4][2], accR[4][2];
        unsigned long long z2 = pk2(0.f, 0.f);
#pragma unroll
        for (int r = 0; r < 4; r++) {
            accL[r][0] = z2; accL[r][1] = z2;
            accR[r][0] = z2; accR[r][1] = z2;
        }
        const float4* Wl4 = (const float4*)Wl;
        const float4* Wr4 = (const float4*)Wr;
        for (int k = 0; k < INC; k++) {
            float4 wl = Wl4[k * 32 + tx];
            float4 wr = Wr4[k * 32 + tx];
            unsigned long long wl0 = pk2(wl.x, wl.y), wl1 = pk2(wl.z, wl.w);
            unsigned long long wr0 = pk2(wr.x, wr.y), wr1 = pk2(wr.z, wr.w);
#pragma unroll
            for (int r = 0; r < 4; r++) {
                float xv = xs[ty + r * 8][k];
                unsigned long long xv2 = pk2(xv, xv);
                fma2(accL[r][0], xv2, wl0, accL[r][0]);
                fma2(accL[r][1], xv2, wl1, accL[r][1]);
                fma2(accR[r][0], xv2, wr0, accR[r][0]);
                fma2(accR[r][1], xv2, wr1, accR[r][1]);
            }
        }
        float4 blv = ((const float4*)bl)[tx];
        float4 brv = ((const float4*)br)[tx];
#pragma unroll
        for (int r = 0; r < 4; r++) {
            int row = row0 + ty + r * 8;
            if (row < NN) {
                float2 l0 = upk2(accL[r][0]), l1 = upk2(accL[r][1]);
                float2 r0 = upk2(accR[r][0]), r1 = upk2(accR[r][1]);
                uint2 lo, ro;
                lo.x = pack_h2(l0.y + blv.y, l0.x + blv.x);
                lo.y = pack_h2(l1.y + blv.w, l1.x + blv.z);
                ro.x = pack_h2(r0.y + brv.y, r0.x + brv.x);
                ro.y = pack_h2(r1.y + brv.w, r1.x + brv.z);
                g_xlh[(size_t)row * 32 + tx] = lo;
                g_xrh[(size_t)row * 32 + tx] = ro;
            }
        }
    } else if (b < GEMM_NB + DEG_NB) {
        // ---------------- deg/attr scatter part ----------------
        int e = (b - GEMM_NB) * 256 + tid;
        if (e < EE) {
            int t = ei[EE + e];
            const float4* a4 = (const float4*)&eattr[(long)e * EDIM];
            float4* dst = &((float4*)g_asum)[(long)t * 4];
#pragma unroll
            for (int q = 0; q < 4; q++) red_add_v4(&dst[q], a4[q]);
            atomicAdd(&g_deg[t], 1.f);
        }
    } else {
        // ---------------- zero part ----------------
        long i = (long)(b - GEMM_NB - DEG_NB) * 256 + tid;
        long stride = (long)ZERO_NB * 256;
        float4* acc = (float4*)g_accum;
        for (long j = i; j < (long)NN * 32; j += stride)
            acc[j] = make_float4(0.f, 0.f, 0.f, 0.f);
        for (long j = i; j < (long)NN * HH; j += stride) g_denom[j] = 0.f;
    }
}

// ---------------- kernel 2: FUSED mma edge projection + edge pass ----------
// Persistent warps grid-stride over 16-edge batches. Per batch: E(16x128) =
// attr @ W_e via 16x mma.m16n8k16 (W_e B-fragments cached in regs once per
// warp), fragments parked in padded smem (stride 68 words), then the 16
// edges are processed: gather xl/xr fp16, score, exp (no max-sub: alpha
// identical, bounded), scatter denom + exp*xl via RED.v4.
// Pure-edge batches (base+16<=EE) prefetch all 32 indices with 2 LDG and
// distribute via SHFL.
#define SMS 68   // smem row stride in words
__global__ void __launch_bounds__(256)
edge_mma_fused(const int* __restrict__ ei,
               const float* __restrict__ eattr,
               const float* __restrict__ We,
               const float* __restrict__ att) {
    __shared__ unsigned es[8][16 * SMS];
    int lane = threadIdx.x & 31;
    int w = threadIdx.x >> 5;
    unsigned* sm = es[w];
    int grp = lane >> 2, ctg = lane & 3;

    // B fragments for all 16 n-tiles (once per warp)
    unsigned b0[16], b1[16];
#pragma unroll
    for (int t = 0; t < 16; t++) {
        int col = t * 8 + grp;
        float x0 = __ldg(&We[(2 * ctg) * HO + col]);
        float x1 = __ldg(&We[(2 * ctg + 1) * HO + col]);
        float x2 = __ldg(&We[(2 * ctg + 8) * HO + col]);
        float x3 = __ldg(&We[(2 * ctg + 9) * HO + col]);
        b0[t] = pack_h2(x1, x0);
        b1[t] = pack_h2(x3, x2);
    }
    float4 av = __ldg(&((const float4*)att)[lane]);

    // consumer smem word offset for this lane's channel quad
    int pw = (lane >> 1) * 4 + 2 * (lane & 1);

    long warp0 = (long)blockIdx.x * 8 + w;
    long nwarp = (long)gridDim.x * 8;

    for (long batch = warp0; batch < NBATCH; batch += nwarp) {
        long base = batch * 16;
        bool pure = (base + 16 <= EE);

        // prefetched indices for pure batches: lanes 0-15 src, 16-31 tgt
        int idxreg = 0;
        if (pure)
            idxreg = (lane < 16) ? __ldg(&ei[base + lane])
                                 : __ldg(&ei[EE + base + lane - 16]);

        // ---- A fragments: rows base+grp (a0,a2), base+grp+8 (a1,a3) ----
        unsigned a0, a1, a2, a3;
        if (pure) {
            const float* p0 = &eattr[(base + grp) * EDIM];
            float2 lo = *(const float2*)(p0 + 2 * ctg);
            float2 hi = *(const float2*)(p0 + 2 * ctg + 8);
            a0 = pack_h2(lo.y, lo.x);
            a2 = pack_h2(hi.y, hi.x);
            const float* p1 = &eattr[(base + grp + 8) * EDIM];
            float2 lo1 = *(const float2*)(p1 + 2 * ctg);
            float2 hi1 = *(const float2*)(p1 + 2 * ctg + 8);
            a1 = pack_h2(lo1.y, lo1.x);
            a3 = pack_h2(hi1.y, hi1.x);
        } else {
            {
                long row = base + grp;
                const float* p; float inv = 1.f;
                if (row < EE) { p = &eattr[row * EDIM]; }
                else { int n = (int)(row - EE); p = &g_asum[(size_t)n * EDIM];
                       inv = 1.f / fmaxf(g_deg[n], 1.f); }
                float2 lo = *(const float2*)(p + 2 * ctg);
                float2 hi = *(const float2*)(p + 2 * ctg + 8);
                a0 = pack_h2(lo.y * inv, lo.x * inv);
                a2 = pack_h2(hi.y * inv, hi.x * inv);
            }
            {
                long row = base + grp + 8;
                const float* p; float inv = 1.f;
                if (row < EE) { p = &eattr[row * EDIM]; }
                else { int n = (int)(row - EE); p = &g_asum[(size_t)n * EDIM];
                       inv = 1.f / fmaxf(g_deg[n], 1.f); }
                float2 lo = *(const float2*)(p + 2 * ctg);
                float2 hi = *(const float2*)(p + 2 * ctg + 8);
                a1 = pack_h2(lo.y * inv, lo.x * inv);
                a3 = pack_h2(hi.y * inv, hi.x * inv);
            }
        }

        // ---- 16 mma -> smem fragments ----
        float z = 0.f;
#pragma unroll
        for (int t = 0; t < 16; t++) {
            float d0, d1, d2, d3;
            asm volatile(
                "mma.sync.aligned.m16n8k16.row.col.f32.f16.f16.f32 "
                "{%0,%1,%2,%3}, {%4,%5,%6,%7}, {%8,%9}, {%10,%10,%10,%10};"
                : "=f"(d0), "=f"(d1), "=f"(d2), "=f"(d3)
                : "r"(a0), "r"(a1), "r"(a2), "r"(a3),
                  "r"(b0[t]), "r"(b1[t]), "f"(z));
            sm[grp * SMS + t * 4 + ctg]       = pack_h2(d1, d0);
            sm[(grp + 8) * SMS + t * 4 + ctg] = pack_h2(d3, d2);
        }
        __syncwarp();

        // ---- process the 16 edges of this batch ----
#pragma unroll 4
        for (int g16 = 0; g16 < 16; g16++) {
            int s, t;
            if (pure) {
                s = __shfl_sync(0xffffffffu, idxreg, g16);
                t = __shfl_sync(0xffffffffu, idxreg, 16 + g16);
            } else {
                long ew = base + g16;
                if (ew < EE) { s = __ldg(&ei[ew]); t = __ldg(&ei[EE + ew]); }
                else         { s = t = (int)(ew - EE); }
            }

            uint2 xlh = __ldg(&g_xlh[(size_t)s * 32 + lane]);
            uint2 xrh = __ldg(&g_xrh[(size_t)t * 32 + lane]);
            float2 xl01 = __half22float2(*(__half2*)&xlh.x);
            float2 xl23 = __half22float2(*(__half2*)&xlh.y);
            float2 xr01 = __half22float2(*(__half2*)&xrh.x);
            float2 xr23 = __half22float2(*(__half2*)&xrh.y);

            uint2 ev = *(const uint2*)&sm[g16 * SMS + pw];
            float2 e01 = __half22float2(*(__half2*)&ev.x);
            float2 e23 = __half22float2(*(__half2*)&ev.y);

            float m0 = lrelu(xl01.x + xr01.x + e01.x);
            float m1 = lrelu(xl01.y + xr01.y + e01.y);
            float m2 = lrelu(xl23.x + xr23.x + e23.x);
            float m3 = lrelu(xl23.y + xr23.y + e23.y);
            float p = m0 * av.x + m1 * av.y + m2 * av.z + m3 * av.w;
            p += __shfl_xor_sync(0xffffffffu, p, 4);
            p += __shfl_xor_sync(0xffffffffu, p, 2);
            p += __shfl_xor_sync(0xffffffffu, p, 1);

            float ex = __expf(p);

            if ((lane & 7) == 0)
                atomicAdd(&g_denom[(size_t)t * HH + (lane >> 3)], ex);

            red_add_v4(&g_accum[(long)t * 32 + lane],
                       make_float4(ex * xl01.x, ex * xl01.y,
                                   ex * xl23.x, ex * xl23.y));
        }
        __syncwarp();   // protect smem before next batch overwrites
    }
}

// ---------------- kernel 3: finalize (head mean + bias + LeakyReLU) --------
__global__ void finalize_kernel(const float* __restrict__ bias,
                                float* __restrict__ out) {
    int idx = blockIdx.x * blockDim.x + threadIdx.x;
    if (idx >= NN * OUTC) return;
    int n = idx >> 5, c = idx & 31;
    const float* acc = (const float*)g_accum;
    float sum = 0.f;
#pragma unroll
    for (int hh = 0; hh < HH; hh++)
        sum += acc[(size_t)n * HO + hh * OUTC + c] / g_denom[(size_t)n * HH + hh];
    float o = sum * 0.25f + bias[c];
    out[idx] = lrelu(o);
}

// ---------------- launch ---------------------------------------------------
extern "C" void kernel_launch(void* const* d_in, const int* in_sizes, int n_in,
                              void* d_out, int out_size) {
    const float* x     = (const float*)d_in[0];
    const int*   ei    = (const int*)  d_in[1];
    const float* eattr = (const float*)d_in[2];
    const float* Wl    = (const float*)d_in[3];
    const float* bl    = (const float*)d_in[4];
    const float* Wr    = (const float*)d_in[5];
    const float* br    = (const float*)d_in[6];
    const float* We    = (const float*)d_in[7];
    const float* att   = (const float*)d_in[8];
    const float* bias  = (const float*)d_in[9];
    float* out = (float*)d_out;

    // zero the atomic-accumulated self-loop scratch via memset nodes
    void* p_asum = nullptr; cudaGetSymbolAddress(&p_asum, g_asum);
    void* p_deg  = nullptr; cudaGetSymbolAddress(&p_deg,  g_deg);
    cudaMemsetAsync(p_asum, 0, sizeof(float) * (size_t)NN * EDIM);
    cudaMemsetAsync(p_deg,  0, sizeof(float) * (size_t)NN);

    fat_prologue<<<FAT_NB, 256>>>(x, Wl, bl, Wr, br, ei, eattr);
    edge_mma_fused<<<444, 256>>>(ei, eattr, We, att);
    finalize_kernel<<<(NN * OUTC + 255) / 256, 256>>>(bias, out);
}

// round 14
// speedup vs baseline: 1.1945x; 1.1945x over previous
#include <cuda_runtime.h>
#include <cuda_fp16.h>

#define NN   50000
#define EE   800000
#define INC  128
#define OUTC 32
#define HH   4
#define EDIM 16
#define HO   128          // H*OUT
#define ENF  (EE + NN)    // edges + self loops = 850000 (divisible by 16)
#define NBATCH (ENF / 16) // 53125 mma warp batches
#define SLOPE 0.2f

// fat-kernel block partition (striped by a coprime swizzle)
#define GEMM_NB 391       // ceil(NN/128), 128 rows per block (tensor-core GEMM)
#define DEG_NB  3125      // ceil(EE/256)
#define ZERO_NB 512
#define FAT_NB  (GEMM_NB + DEG_NB + ZERO_NB)   // 4028 = 4*19*53
#define FAT_SWZ 1999      // coprime with 4028

// W fragment smem: 2 matrices x 128 cols x 68-word padded rows
#define WSTRIDE 68
#define WWORDS  (128 * WSTRIDE)          // 8704 words per matrix
#define FAT_SMEM (2 * WWORDS * 4)        // 69632 bytes

// ---------------- scratch (device globals; no allocation allowed) ----------
__device__ uint2    g_xlh[(size_t)NN * 32];      // x@W_l+b_l fp16 (12.8 MB)
__device__ uint2    g_xrh[(size_t)NN * 32];      // x@W_r+b_r fp16 (12.8 MB)
__device__ float    g_deg[NN];                   // in-degree
__device__ float    g_asum[(size_t)NN * EDIM];   // scatter-sum of edge attrs
__device__ float    g_denom[(size_t)NN * HH];    // softmax denominators
__device__ float4   g_accum[(size_t)NN * OUTC];  // sum exp(s)*x_l[src] (25.6 MB)

// ---------------- helpers --------------------------------------------------
__device__ __forceinline__ float lrelu(float v) { return fmaxf(v, SLOPE * v); }

__device__ __forceinline__ void red_add_v4(float4* addr, float4 v) {
    asm volatile("red.global.add.v4.f32 [%0], {%1,%2,%3,%4};"
                 :: "l"(addr), "f"(v.x), "f"(v.y), "f"(v.z), "f"(v.w)
                 : "memory");
}

// pack two f32 into f16x2: lo -> bits[15:0], hi -> bits[31:16]
__device__ __forceinline__ unsigned pack_h2(float hi, float lo) {
    unsigned r;
    asm("cvt.rn.f16x2.f32 %0, %1, %2;" : "=r"(r) : "f"(hi), "f"(lo));
    return r;
}

// ---------------- kernel 1: FAT prologue (striped block types) --------------
// gemm blocks: x@W_l / x@W_r via mma.m16n8k16, W fragments staged in smem
// deg blocks:  degree + attr scatter-sum
// zero blocks: zero accum + denom
__global__ void __launch_bounds__(256)
fat_prologue(const float* __restrict__ x,
             const float* __restrict__ Wl, const float* __restrict__ bl,
             const float* __restrict__ Wr, const float* __restrict__ br,
             const int* __restrict__ ei,
             const float* __restrict__ eattr) {
    extern __shared__ unsigned wfrag[];   // [2][WWORDS]
    int b = (int)(((long)blockIdx.x * FAT_SWZ) % FAT_NB);
    int tid = threadIdx.x;

    if (b < GEMM_NB) {
        // ---- fill W fragment smem (pre-permuted b-frag words) ----
        // word(n, p) = (W[2p][n], W[2p+1][n]) at n*WSTRIDE + q*8 + ctg*2 + sel
        // where q=p>>3, r=p&7, ctg=r&3, sel=r>>2
        for (int i = tid; i < 8192; i += 256) {
            int n = i & 127, p = i >> 7;
            int q = p >> 3, r = p & 7;
            int idx = n * WSTRIDE + q * 8 + (r & 3) * 2 + (r >> 2);
            wfrag[idx]          = pack_h2(Wl[(2 * p + 1) * HO + n], Wl[2 * p * HO + n]);
            wfrag[WWORDS + idx] = pack_h2(Wr[(2 * p + 1) * HO + n], Wr[2 * p * HO + n]);
        }
        __syncthreads();

        int w = tid >> 5, lane = tid & 31;
        int grp = lane >> 2, ctg = lane & 3;
        int r0 = b * 128 + w * 16 + grp;
        int r1 = r0 + 8;

        // A fragments for all 8 k-chunks (fp16), rows r0/r1
        unsigned A0[8], A1[8], A2[8], A3[8];
#pragma unroll
        for (int q = 0; q < 8; q++) {
            if (r0 < NN) {
                float2 v0 = *(const float2*)&x[(long)r0 * INC + q * 16 + 2 * ctg];
                float2 v2 = *(const float2*)&x[(long)r0 * INC + q * 16 + 2 * ctg + 8];
                A0[q] = pack_h2(v0.y, v0.x);
                A2[q] = pack_h2(v2.y, v2.x);
            } else { A0[q] = 0u; A2[q] = 0u; }
            if (r1 < NN) {
                float2 v1 = *(const float2*)&x[(long)r1 * INC + q * 16 + 2 * ctg];
                float2 v3 = *(const float2*)&x[(long)r1 * INC + q * 16 + 2 * ctg + 8];
                A1[q] = pack_h2(v1.y, v1.x);
                A3[q] = pack_h2(v3.y, v3.x);
            } else { A1[q] = 0u; A3[q] = 0u; }
        }

#pragma unroll 1
        for (int m = 0; m < 2; m++) {
            const unsigned* wf = wfrag + m * WWORDS;
            const float* bv = m ? br : bl;
            unsigned* dst = m ? (unsigned*)g_xrh : (unsigned*)g_xlh;
#pragma unroll 1
            for (int t = 0; t < 16; t++) {
                float d0 = 0.f, d1 = 0.f, d2 = 0.f, d3 = 0.f;
                const unsigned* wrow = &wf[(t * 8 + grp) * WSTRIDE + ctg * 2];
#pragma unroll
                for (int q = 0; q < 8; q++) {
                    uint2 bb = *(const uint2*)&wrow[q * 8];
                    asm volatile(
                        "mma.sync.aligned.m16n8k16.row.col.f32.f16.f16.f32 "
                        "{%0,%1,%2,%3}, {%4,%5,%6,%7}, {%8,%9}, {%0,%1,%2,%3};"
                        : "+f"(d0), "+f"(d1), "+f"(d2), "+f"(d3)
                        : "r"(A0[q]), "r"(A1[q]), "r"(A2[q]), "r"(A3[q]),
                          "r"(bb.x), "r"(bb.y));
                }
                float2 bb2 = __ldg((const float2*)&bv[t * 8 + 2 * ctg]);
                d0 += bb2.x; d1 += bb2.y; d2 += bb2.x; d3 += bb2.y;
                // D frag: d0=D[grp][2ctg] d1=D[grp][2ctg+1] d2/d3 = rows grp+8
                // output word (u32 = ch pair) index = col/2 = t*4 + ctg
                if (r0 < NN) dst[(size_t)r0 * 64 + t * 4 + ctg] = pack_h2(d1, d0);
                if (r1 < NN) dst[(size_t)r1 * 64 + t * 4 + ctg] = pack_h2(d3, d2);
            }
        }
    } else if (b < GEMM_NB + DEG_NB) {
        // ---------------- deg/attr scatter part ----------------
        int e = (b - GEMM_NB) * 256 + tid;
        if (e < EE) {
            int t = ei[EE + e];
            const float4* a4 = (const float4*)&eattr[(long)e * EDIM];
            float4* dst = &((float4*)g_asum)[(long)t * 4];
#pragma unroll
            for (int q = 0; q < 4; q++) red_add_v4(&dst[q], a4[q]);
            atomicAdd(&g_deg[t], 1.f);
        }
    } else {
        // ---------------- zero part ----------------
        long i = (long)(b - GEMM_NB - DEG_NB) * 256 + tid;
        long stride = (long)ZERO_NB * 256;
        float4* acc = (float4*)g_accum;
        for (long j = i; j < (long)NN * 32; j += stride)
            acc[j] = make_float4(0.f, 0.f, 0.f, 0.f);
        for (long j = i; j < (long)NN * HH; j += stride) g_denom[j] = 0.f;
    }
}

// ---------------- kernel 2: FUSED mma edge projection + edge pass ----------
// Persistent warps grid-stride over 16-edge batches. Per batch: E(16x128) =
// attr @ W_e via 16x mma.m16n8k16 (W_e B-fragments cached in regs once per
// warp), fragments parked in padded smem, then the 16 edges are processed:
// gather xl/xr fp16, score, exp (no max-sub: alpha identical, bounded),
// scatter denom + exp*xl via RED.v4. Pure-edge batches prefetch indices
// with 2 LDG + SHFL.
#define SMS 68   // smem row stride in words
__global__ void __launch_bounds__(256)
edge_mma_fused(const int* __restrict__ ei,
               const float* __restrict__ eattr,
               const float* __restrict__ We,
               const float* __restrict__ att) {
    __shared__ unsigned es[8][16 * SMS];
    int lane = threadIdx.x & 31;
    int w = threadIdx.x >> 5;
    unsigned* sm = es[w];
    int grp = lane >> 2, ctg = lane & 3;

    // B fragments for all 16 n-tiles (once per warp)
    unsigned b0[16], b1[16];
#pragma unroll
    for (int t = 0; t < 16; t++) {
        int col = t * 8 + grp;
        float x0 = __ldg(&We[(2 * ctg) * HO + col]);
        float x1 = __ldg(&We[(2 * ctg + 1) * HO + col]);
        float x2 = __ldg(&We[(2 * ctg + 8) * HO + col]);
        float x3 = __ldg(&We[(2 * ctg + 9) * HO + col]);
        b0[t] = pack_h2(x1, x0);
        b1[t] = pack_h2(x3, x2);
    }
    float4 av = __ldg(&((const float4*)att)[lane]);

    // consumer smem word offset for this lane's channel quad
    int pw = (lane >> 1) * 4 + 2 * (lane & 1);

    long warp0 = (long)blockIdx.x * 8 + w;
    long nwarp = (long)gridDim.x * 8;

    for (long batch = warp0; batch < NBATCH; batch += nwarp) {
        long base = batch * 16;
        bool pure = (base + 16 <= EE);

        // prefetched indices for pure batches: lanes 0-15 src, 16-31 tgt
        int idxreg = 0;
        if (pure)
            idxreg = (lane < 16) ? __ldg(&ei[base + lane])
                                 : __ldg(&ei[EE + base + lane - 16]);

        // ---- A fragments: rows base+grp (a0,a2), base+grp+8 (a1,a3) ----
        unsigned a0, a1, a2, a3;
        if (pure) {
            const float* p0 = &eattr[(base + grp) * EDIM];
            float2 lo = *(const float2*)(p0 + 2 * ctg);
            float2 hi = *(const float2*)(p0 + 2 * ctg + 8);
            a0 = pack_h2(lo.y, lo.x);
            a2 = pack_h2(hi.y, hi.x);
            const float* p1 = &eattr[(base + grp + 8) * EDIM];
            float2 lo1 = *(const float2*)(p1 + 2 * ctg);
            float2 hi1 = *(const float2*)(p1 + 2 * ctg + 8);
            a1 = pack_h2(lo1.y, lo1.x);
            a3 = pack_h2(hi1.y, hi1.x);
        } else {
            {
                long row = base + grp;
                const float* p; float inv = 1.f;
                if (row < EE) { p = &eattr[row * EDIM]; }
                else { int n = (int)(row - EE); p = &g_asum[(size_t)n * EDIM];
                       inv = 1.f / fmaxf(g_deg[n], 1.f); }
                float2 lo = *(const float2*)(p + 2 * ctg);
                float2 hi = *(const float2*)(p + 2 * ctg + 8);
                a0 = pack_h2(lo.y * inv, lo.x * inv);
                a2 = pack_h2(hi.y * inv, hi.x * inv);
            }
            {
                long row = base + grp + 8;
                const float* p; float inv = 1.f;
                if (row < EE) { p = &eattr[row * EDIM]; }
                else { int n = (int)(row - EE); p = &g_asum[(size_t)n * EDIM];
                       inv = 1.f / fmaxf(g_deg[n], 1.f); }
                float2 lo = *(const float2*)(p + 2 * ctg);
                float2 hi = *(const float2*)(p + 2 * ctg + 8);
                a1 = pack_h2(lo.y * inv, lo.x * inv);
                a3 = pack_h2(hi.y * inv, hi.x * inv);
            }
        }

        // ---- 16 mma -> smem fragments ----
        float z = 0.f;
#pragma unroll
        for (int t = 0; t < 16; t++) {
            float d0, d1, d2, d3;
            asm volatile(
                "mma.sync.aligned.m16n8k16.row.col.f32.f16.f16.f32 "
                "{%0,%1,%2,%3}, {%4,%5,%6,%7}, {%8,%9}, {%10,%10,%10,%10};"
                : "=f"(d0), "=f"(d1), "=f"(d2), "=f"(d3)
                : "r"(a0), "r"(a1), "r"(a2), "r"(a3),
                  "r"(b0[t]), "r"(b1[t]), "f"(z));
            sm[grp * SMS + t * 4 + ctg]       = pack_h2(d1, d0);
            sm[(grp + 8) * SMS + t * 4 + ctg] = pack_h2(d3, d2);
        }
        __syncwarp();

        // ---- process the 16 edges of this batch ----
#pragma unroll 4
        for (int g16 = 0; g16 < 16; g16++) {
            int s, t;
            if (pure) {
                s = __shfl_sync(0xffffffffu, idxreg, g16);
                t = __shfl_sync(0xffffffffu, idxreg, 16 + g16);
            } else {
                long ew = base + g16;
                if (ew < EE) { s = __ldg(&ei[ew]); t = __ldg(&ei[EE + ew]); }
                else         { s = t = (int)(ew - EE); }
            }

            uint2 xlh = __ldg(&g_xlh[(size_t)s * 32 + lane]);
            uint2 xrh = __ldg(&g_xrh[(size_t)t * 32 + lane]);
            float2 xl01 = __half22float2(*(__half2*)&xlh.x);
            float2 xl23 = __half22float2(*(__half2*)&xlh.y);
            float2 xr01 = __half22float2(*(__half2*)&xrh.x);
            float2 xr23 = __half22float2(*(__half2*)&xrh.y);

            uint2 ev = *(const uint2*)&sm[g16 * SMS + pw];
            float2 e01 = __half22float2(*(__half2*)&ev.x);
            float2 e23 = __half22float2(*(__half2*)&ev.y);

            float m0 = lrelu(xl01.x + xr01.x + e01.x);
            float m1 = lrelu(xl01.y + xr01.y + e01.y);
            float m2 = lrelu(xl23.x + xr23.x + e23.x);
            float m3 = lrelu(xl23.y + xr23.y + e23.y);
            float p = m0 * av.x + m1 * av.y + m2 * av.z + m3 * av.w;
            p += __shfl_xor_sync(0xffffffffu, p, 4);
            p += __shfl_xor_sync(0xffffffffu, p, 2);
            p += __shfl_xor_sync(0xffffffffu, p, 1);

            float ex = __expf(p);

            if ((lane & 7) == 0)
                atomicAdd(&g_denom[(size_t)t * HH + (lane >> 3)], ex);

            red_add_v4(&g_accum[(long)t * 32 + lane],
                       make_float4(ex * xl01.x, ex * xl01.y,
                                   ex * xl23.x, ex * xl23.y));
        }
        __syncwarp();   // protect smem before next batch overwrites
    }
}

// ---------------- kernel 3: finalize (head mean + bias + LeakyReLU) --------
__global__ void finalize_kernel(const float* __restrict__ bias,
                                float* __restrict__ out) {
    int idx = blockIdx.x * blockDim.x + threadIdx.x;
    if (idx >= NN * OUTC) return;
    int n = idx >> 5, c = idx & 31;
    const float* acc = (const float*)g_accum;
    float sum = 0.f;
#pragma unroll
    for (int hh = 0; hh < HH; hh++)
        sum += acc[(size_t)n * HO + hh * OUTC + c] / g_denom[(size_t)n * HH + hh];
    float o = sum * 0.25f + bias[c];
    out[idx] = lrelu(o);
}

// ---------------- launch ---------------------------------------------------
extern "C" void kernel_launch(void* const* d_in, const int* in_sizes, int n_in,
                              void* d_out, int out_size) {
    const float* x     = (const float*)d_in[0];
    const int*   ei    = (const int*)  d_in[1];
    const float* eattr = (const float*)d_in[2];
    const float* Wl    = (const float*)d_in[3];
    const float* bl    = (const float*)d_in[4];
    const float* Wr    = (const float*)d_in[5];
    const float* br    = (const float*)d_in[6];
    const float* We    = (const float*)d_in[7];
    const float* att   = (const float*)d_in[8];
    const float* bias  = (const float*)d_in[9];
    float* out = (float*)d_out;

    // zero the atomic-accumulated self-loop scratch via memset nodes
    void* p_asum = nullptr; cudaGetSymbolAddress(&p_asum, g_asum);
    void* p_deg  = nullptr; cudaGetSymbolAddress(&p_deg,  g_deg);
    cudaMemsetAsync(p_asum, 0, sizeof(float) * (size_t)NN * EDIM);
    cudaMemsetAsync(p_deg,  0, sizeof(float) * (size_t)NN);

    cudaFuncSetAttribute(fat_prologue,
                         cudaFuncAttributeMaxDynamicSharedMemorySize, FAT_SMEM);
    fat_prologue<<<FAT_NB, 256, FAT_SMEM>>>(x, Wl, bl, Wr, br, ei, eattr);
    edge_mma_fused<<<444, 256>>>(ei, eattr, We, att);
    finalize_kernel<<<(NN * OUTC + 255) / 256, 256>>>(bias, out);
}

// round 15
// speedup vs baseline: 1.2903x; 1.0801x over previous
#include <cuda_runtime.h>
#include <cuda_fp16.h>

#define NN   50000
#define EE   800000
#define INC  128
#define OUTC 32
#define HH   4
#define EDIM 16
#define HO   128          // H*OUT
#define ENF  (EE + NN)    // edges + self loops = 850000 (divisible by 16)
#define NBATCH (ENF / 16) // 53125 mma warp batches
#define SLOPE 0.2f

// fat-kernel block partition (striped by a coprime swizzle)
#define GEMM_NB 391       // ceil(NN/128), 128 rows per block (tensor-core GEMM)
#define DEG_NB  3125      // ceil(EE/256)
#define ZERO_NB 512
#define FAT_NB  (GEMM_NB + DEG_NB + ZERO_NB)   // 4028
#define FAT_SWZ 1999      // coprime with 4028

// W fragment smem for fat kernel: 2 matrices x 128 cols x 68-word padded rows
#define WSTRIDE 68
#define WWORDS  (128 * WSTRIDE)
#define FAT_SMEM (2 * WWORDS * 4)        // 69632 bytes

// ---------------- scratch (device globals; no allocation allowed) ----------
__device__ uint2    g_xlh[(size_t)NN * 32];      // x@W_l+b_l fp16 (12.8 MB)
__device__ uint2    g_xrh[(size_t)NN * 32];      // x@W_r+b_r fp16 (12.8 MB)
__device__ float    g_deg[NN];                   // in-degree
__device__ float    g_asum[(size_t)NN * EDIM];   // scatter-sum of edge attrs
__device__ float    g_denom[(size_t)NN * HH];    // softmax denominators
__device__ float4   g_accum[(size_t)NN * OUTC];  // sum exp(s)*x_l[src] (25.6 MB)

// ---------------- helpers --------------------------------------------------
__device__ __forceinline__ float lrelu(float v) { return fmaxf(v, SLOPE * v); }

__device__ __forceinline__ void red_add_v4(float4* addr, float4 v) {
    asm volatile("red.global.add.v4.f32 [%0], {%1,%2,%3,%4};"
                 :: "l"(addr), "f"(v.x), "f"(v.y), "f"(v.z), "f"(v.w)
                 : "memory");
}

// pack two f32 into f16x2: lo -> bits[15:0], hi -> bits[31:16]
__device__ __forceinline__ unsigned pack_h2(float hi, float lo) {
    unsigned r;
    asm("cvt.rn.f16x2.f32 %0, %1, %2;" : "=r"(r) : "f"(hi), "f"(lo));
    return r;
}

// ---------------- kernel 1: FAT prologue (striped block types) --------------
// gemm blocks: x@W_l / x@W_r via mma.m16n8k16, W fragments staged in smem
// deg blocks:  degree + attr scatter-sum
// zero blocks: zero accum + denom
__global__ void __launch_bounds__(256)
fat_prologue(const float* __restrict__ x,
             const float* __restrict__ Wl, const float* __restrict__ bl,
             const float* __restrict__ Wr, const float* __restrict__ br,
             const int* __restrict__ ei,
             const float* __restrict__ eattr) {
    extern __shared__ unsigned wfrag[];   // [2][WWORDS]
    int b = (int)(((long)blockIdx.x * FAT_SWZ) % FAT_NB);
    int tid = threadIdx.x;

    if (b < GEMM_NB) {
        // ---- fill W fragment smem (pre-permuted b-frag words) ----
        for (int i = tid; i < 8192; i += 256) {
            int n = i & 127, p = i >> 7;
            int q = p >> 3, r = p & 7;
            int idx = n * WSTRIDE + q * 8 + (r & 3) * 2 + (r >> 2);
            wfrag[idx]          = pack_h2(Wl[(2 * p + 1) * HO + n], Wl[2 * p * HO + n]);
            wfrag[WWORDS + idx] = pack_h2(Wr[(2 * p + 1) * HO + n], Wr[2 * p * HO + n]);
        }
        __syncthreads();

        int w = tid >> 5, lane = tid & 31;
        int grp = lane >> 2, ctg = lane & 3;
        int r0 = b * 128 + w * 16 + grp;
        int r1 = r0 + 8;

        // A fragments for all 8 k-chunks (fp16), rows r0/r1
        unsigned A0[8], A1[8], A2[8], A3[8];
#pragma unroll
        for (int q = 0; q < 8; q++) {
            if (r0 < NN) {
                float2 v0 = *(const float2*)&x[(long)r0 * INC + q * 16 + 2 * ctg];
                float2 v2 = *(const float2*)&x[(long)r0 * INC + q * 16 + 2 * ctg + 8];
                A0[q] = pack_h2(v0.y, v0.x);
                A2[q] = pack_h2(v2.y, v2.x);
            } else { A0[q] = 0u; A2[q] = 0u; }
            if (r1 < NN) {
                float2 v1 = *(const float2*)&x[(long)r1 * INC + q * 16 + 2 * ctg];
                float2 v3 = *(const float2*)&x[(long)r1 * INC + q * 16 + 2 * ctg + 8];
                A1[q] = pack_h2(v1.y, v1.x);
                A3[q] = pack_h2(v3.y, v3.x);
            } else { A1[q] = 0u; A3[q] = 0u; }
        }

#pragma unroll 1
        for (int m = 0; m < 2; m++) {
            const unsigned* wf = wfrag + m * WWORDS;
            const float* bv = m ? br : bl;
            unsigned* dst = m ? (unsigned*)g_xrh : (unsigned*)g_xlh;
#pragma unroll 1
            for (int t = 0; t < 16; t++) {
                float d0 = 0.f, d1 = 0.f, d2 = 0.f, d3 = 0.f;
                const unsigned* wrow = &wf[(t * 8 + grp) * WSTRIDE + ctg * 2];
#pragma unroll
                for (int q = 0; q < 8; q++) {
                    uint2 bb = *(const uint2*)&wrow[q * 8];
                    asm volatile(
                        "mma.sync.aligned.m16n8k16.row.col.f32.f16.f16.f32 "
                        "{%0,%1,%2,%3}, {%4,%5,%6,%7}, {%8,%9}, {%0,%1,%2,%3};"
                        : "+f"(d0), "+f"(d1), "+f"(d2), "+f"(d3)
                        : "r"(A0[q]), "r"(A1[q]), "r"(A2[q]), "r"(A3[q]),
                          "r"(bb.x), "r"(bb.y));
                }
                float2 bb2 = __ldg((const float2*)&bv[t * 8 + 2 * ctg]);
                d0 += bb2.x; d1 += bb2.y; d2 += bb2.x; d3 += bb2.y;
                if (r0 < NN) dst[(size_t)r0 * 64 + t * 4 + ctg] = pack_h2(d1, d0);
                if (r1 < NN) dst[(size_t)r1 * 64 + t * 4 + ctg] = pack_h2(d3, d2);
            }
        }
    } else if (b < GEMM_NB + DEG_NB) {
        // ---------------- deg/attr scatter part ----------------
        int e = (b - GEMM_NB) * 256 + tid;
        if (e < EE) {
            int t = ei[EE + e];
            const float4* a4 = (const float4*)&eattr[(long)e * EDIM];
            float4* dst = &((float4*)g_asum)[(long)t * 4];
#pragma unroll
            for (int q = 0; q < 4; q++) red_add_v4(&dst[q], a4[q]);
            atomicAdd(&g_deg[t], 1.f);
        }
    } else {
        // ---------------- zero part ----------------
        long i = (long)(b - GEMM_NB - DEG_NB) * 256 + tid;
        long stride = (long)ZERO_NB * 256;
        float4* acc = (float4*)g_accum;
        for (long j = i; j < (long)NN * 32; j += stride)
            acc[j] = make_float4(0.f, 0.f, 0.f, 0.f);
        for (long j = i; j < (long)NN * HH; j += stride) g_denom[j] = 0.f;
    }
}

// ---------------- kernel 2: FUSED mma edge projection + edge pass ----------
// Persistent warps grid-stride over 16-edge batches. W_e B-fragments live in
// BLOCK-shared smem (4 KB, loaded once) instead of per-warp registers,
// cutting regs ~79 -> ~50 so 4-5 blocks/SM fit. Per batch: 16x mma.m16n8k16
// -> padded smem fragments -> 16 edges: gather xl/xr fp16, score, exp (no
// max-sub: alpha identical, bounded), scatter denom + exp*xl via RED.v4.
#define SMS 68   // smem row stride in words
__global__ void __launch_bounds__(256, 4)
edge_mma_fused(const int* __restrict__ ei,
               const float* __restrict__ eattr,
               const float* __restrict__ We,
               const float* __restrict__ att) {
    __shared__ unsigned es[8][16 * SMS];
    __shared__ unsigned wsh[16 * 64];   // [t][lane][sel] = t*64 + lane*2 + sel
    int lane = threadIdx.x & 31;
    int w = threadIdx.x >> 5;
    unsigned* sm = es[w];
    int grp = lane >> 2, ctg = lane & 3;

    // ---- block-shared W_e B-fragments: i = t*32 + lane ----
    for (int i = threadIdx.x; i < 512; i += 256) {
        int t = i >> 5, ln = i & 31;
        int g2 = ln >> 2, c2 = ln & 3;
        int col = t * 8 + g2;
        float x0 = __ldg(&We[(2 * c2) * HO + col]);
        float x1 = __ldg(&We[(2 * c2 + 1) * HO + col]);
        float x2 = __ldg(&We[(2 * c2 + 8) * HO + col]);
        float x3 = __ldg(&We[(2 * c2 + 9) * HO + col]);
        wsh[t * 64 + ln * 2]     = pack_h2(x1, x0);
        wsh[t * 64 + ln * 2 + 1] = pack_h2(x3, x2);
    }
    __syncthreads();

    float4 av = __ldg(&((const float4*)att)[lane]);

    // consumer smem word offset for this lane's channel quad
    int pw = (lane >> 1) * 4 + 2 * (lane & 1);

    long warp0 = (long)blockIdx.x * 8 + w;
    long nwarp = (long)gridDim.x * 8;

    for (long batch = warp0; batch < NBATCH; batch += nwarp) {
        long base = batch * 16;
        bool pure = (base + 16 <= EE);

        // prefetched indices for pure batches: lanes 0-15 src, 16-31 tgt
        int idxreg = 0;
        if (pure)
            idxreg = (lane < 16) ? __ldg(&ei[base + lane])
                                 : __ldg(&ei[EE + base + lane - 16]);

        // ---- A fragments: rows base+grp (a0,a2), base+grp+8 (a1,a3) ----
        unsigned a0, a1, a2, a3;
        if (pure) {
            const float* p0 = &eattr[(base + grp) * EDIM];
            float2 lo = *(const float2*)(p0 + 2 * ctg);
            float2 hi = *(const float2*)(p0 + 2 * ctg + 8);
            a0 = pack_h2(lo.y, lo.x);
            a2 = pack_h2(hi.y, hi.x);
            const float* p1 = &eattr[(base + grp + 8) * EDIM];
            float2 lo1 = *(const float2*)(p1 + 2 * ctg);
            float2 hi1 = *(const float2*)(p1 + 2 * ctg + 8);
            a1 = pack_h2(lo1.y, lo1.x);
            a3 = pack_h2(hi1.y, hi1.x);
        } else {
            {
                long row = base + grp;
                const float* p; float inv = 1.f;
                if (row < EE) { p = &eattr[row * EDIM]; }
                else { int n = (int)(row - EE); p = &g_asum[(size_t)n * EDIM];
                       inv = 1.f / fmaxf(g_deg[n], 1.f); }
                float2 lo = *(const float2*)(p + 2 * ctg);
                float2 hi = *(const float2*)(p + 2 * ctg + 8);
                a0 = pack_h2(lo.y * inv, lo.x * inv);
                a2 = pack_h2(hi.y * inv, hi.x * inv);
            }
            {
                long row = base + grp + 8;
                const float* p; float inv = 1.f;
                if (row < EE) { p = &eattr[row * EDIM]; }
                else { int n = (int)(row - EE); p = &g_asum[(size_t)n * EDIM];
                       inv = 1.f / fmaxf(g_deg[n], 1.f); }
                float2 lo = *(const float2*)(p + 2 * ctg);
                float2 hi = *(const float2*)(p + 2 * ctg + 8);
                a1 = pack_h2(lo.y * inv, lo.x * inv);
                a3 = pack_h2(hi.y * inv, hi.x * inv);
            }
        }

        // ---- 16 mma -> smem fragments (B-frag from block smem) ----
        float z = 0.f;
#pragma unroll
        for (int t = 0; t < 16; t++) {
            uint2 bb = *(const uint2*)&wsh[t * 64 + lane * 2];
            float d0, d1, d2, d3;
            asm volatile(
                "mma.sync.aligned.m16n8k16.row.col.f32.f16.f16.f32 "
                "{%0,%1,%2,%3}, {%4,%5,%6,%7}, {%8,%9}, {%10,%10,%10,%10};"
                : "=f"(d0), "=f"(d1), "=f"(d2), "=f"(d3)
                : "r"(a0), "r"(a1), "r"(a2), "r"(a3),
                  "r"(bb.x), "r"(bb.y), "f"(z));
            sm[grp * SMS + t * 4 + ctg]       = pack_h2(d1, d0);
            sm[(grp + 8) * SMS + t * 4 + ctg] = pack_h2(d3, d2);
        }
        __syncwarp();

        // ---- process the 16 edges of this batch ----
#pragma unroll 4
        for (int g16 = 0; g16 < 16; g16++) {
            int s, t;
            if (pure) {
                s = __shfl_sync(0xffffffffu, idxreg, g16);
                t = __shfl_sync(0xffffffffu, idxreg, 16 + g16);
            } else {
                long ew = base + g16;
                if (ew < EE) { s = __ldg(&ei[ew]); t = __ldg(&ei[EE + ew]); }
                else         { s = t = (int)(ew - EE); }
            }

            uint2 xlh = __ldg(&g_xlh[(size_t)s * 32 + lane]);
            uint2 xrh = __ldg(&g_xrh[(size_t)t * 32 + lane]);
            float2 xl01 = __half22float2(*(__half2*)&xlh.x);
            float2 xl23 = __half22float2(*(__half2*)&xlh.y);
            float2 xr01 = __half22float2(*(__half2*)&xrh.x);
            float2 xr23 = __half22float2(*(__half2*)&xrh.y);

            uint2 ev = *(const uint2*)&sm[g16 * SMS + pw];
            float2 e01 = __half22float2(*(__half2*)&ev.x);
            float2 e23 = __half22float2(*(__half2*)&ev.y);

            float m0 = lrelu(xl01.x + xr01.x + e01.x);
            float m1 = lrelu(xl01.y + xr01.y + e01.y);
            float m2 = lrelu(xl23.x + xr23.x + e23.x);
            float m3 = lrelu(xl23.y + xr23.y + e23.y);
            float p = m0 * av.x + m1 * av.y + m2 * av.z + m3 * av.w;
            p += __shfl_xor_sync(0xffffffffu, p, 4);
            p += __shfl_xor_sync(0xffffffffu, p, 2);
            p += __shfl_xor_sync(0xffffffffu, p, 1);

            float ex = __expf(p);

            if ((lane & 7) == 0)
                atomicAdd(&g_denom[(size_t)t * HH + (lane >> 3)], ex);

            red_add_v4(&g_accum[(long)t * 32 + lane],
                       make_float4(ex * xl01.x, ex * xl01.y,
                                   ex * xl23.x, ex * xl23.y));
        }
        __syncwarp();   // protect smem before next batch overwrites
    }
}

// ---------------- kernel 3: finalize (head mean + bias + LeakyReLU) --------
__global__ void finalize_kernel(const float* __restrict__ bias,
                                float* __restrict__ out) {
    int idx = blockIdx.x * blockDim.x + threadIdx.x;
    if (idx >= NN * OUTC) return;
    int n = idx >> 5, c = idx & 31;
    const float* acc = (const float*)g_accum;
    float sum = 0.f;
#pragma unroll
    for (int hh = 0; hh < HH; hh++)
        sum += acc[(size_t)n * HO + hh * OUTC + c] / g_denom[(size_t)n * HH + hh];
    float o = sum * 0.25f + bias[c];
    out[idx] = lrelu(o);
}

// ---------------- launch ---------------------------------------------------
extern "C" void kernel_launch(void* const* d_in, const int* in_sizes, int n_in,
                              void* d_out, int out_size) {
    const float* x     = (const float*)d_in[0];
    const int*   ei    = (const int*)  d_in[1];
    const float* eattr = (const float*)d_in[2];
    const float* Wl    = (const float*)d_in[3];
    const float* bl    = (const float*)d_in[4];
    const float* Wr    = (const float*)d_in[5];
    const float* br    = (const float*)d_in[6];
    const float* We    = (const float*)d_in[7];
    const float* att   = (const float*)d_in[8];
    const float* bias  = (const float*)d_in[9];
    float* out = (float*)d_out;

    // zero the atomic-accumulated self-loop scratch via memset nodes
    void* p_asum = nullptr; cudaGetSymbolAddress(&p_asum, g_asum);
    void* p_deg  = nullptr; cudaGetSymbolAddress(&p_deg,  g_deg);
    cudaMemsetAsync(p_asum, 0, sizeof(float) * (size_t)NN * EDIM);
    cudaMemsetAsync(p_deg,  0, sizeof(float) * (size_t)NN);

    cudaFuncSetAttribute(fat_prologue,
                         cudaFuncAttributeMaxDynamicSharedMemorySize, FAT_SMEM);
    fat_prologue<<<FAT_NB, 256, FAT_SMEM>>>(x, Wl, bl, Wr, br, ei, eattr);
    edge_mma_fused<<<592, 256>>>(ei, eattr, We, att);
    finalize_kernel<<<(NN * OUTC + 255) / 256, 256>>>(bias, out);
}

// round 16
// speedup vs baseline: 1.3056x; 1.0119x over previous
#include <cuda_runtime.h>
#include <cuda_fp16.h>

#define NN   50000
#define EE   800000
#define INC  128
#define OUTC 32
#define HH   4
#define EDIM 16
#define HO   128          // H*OUT
#define ENF  (EE + NN)    // edges + self loops = 850000 (divisible by 16)
#define NBATCH (ENF / 16) // 53125 mma warp batches
#define SLOPE 0.2f

// fat-kernel block partition (striped by a coprime swizzle)
#define GEMM_NB 782       // 2 * ceil(NN/128): 128 rows x 64 cols per block
#define DEG_NB  782       // 1024 edges per block (4 x 256)
#define ZERO_NB 256
#define FAT_NB  (GEMM_NB + DEG_NB + ZERO_NB)   // 1820
#define FAT_SWZ 739       // coprime with 1820

// W fragment smem: 2 matrices x 64 cols x 68-word padded rows
#define WSTRIDE 68
#define WWORDS  (64 * WSTRIDE)           // 4352 words per matrix half
#define FAT_SMEM (2 * WWORDS * 4)        // 34816 bytes

// ---------------- scratch (device globals; no allocation allowed) ----------
__device__ uint2    g_xlh[(size_t)NN * 32];      // x@W_l+b_l fp16 (12.8 MB)
__device__ uint2    g_xrh[(size_t)NN * 32];      // x@W_r+b_r fp16 (12.8 MB)
__device__ float    g_deg[NN];                   // in-degree
__device__ float    g_asum[(size_t)NN * EDIM];   // scatter-sum of edge attrs
__device__ float    g_denom[(size_t)NN * HH];    // softmax denominators
__device__ float4   g_accum[(size_t)NN * OUTC];  // sum exp(s)*x_l[src] (25.6 MB)

// ---------------- helpers --------------------------------------------------
__device__ __forceinline__ float lrelu(float v) { return fmaxf(v, SLOPE * v); }

__device__ __forceinline__ void red_add_v4(float4* addr, float4 v) {
    asm volatile("red.global.add.v4.f32 [%0], {%1,%2,%3,%4};"
                 :: "l"(addr), "f"(v.x), "f"(v.y), "f"(v.z), "f"(v.w)
                 : "memory");
}

// pack two f32 into f16x2: lo -> bits[15:0], hi -> bits[31:16]
__device__ __forceinline__ unsigned pack_h2(float hi, float lo) {
    unsigned r;
    asm("cvt.rn.f16x2.f32 %0, %1, %2;" : "=r"(r) : "f"(hi), "f"(lo));
    return r;
}

// ---------------- kernel 1: FAT prologue (striped block types) --------------
// gemm blocks: x@W_{l,r} via mma.m16n8k16, 128 rows x 64 cols per block,
//              W fragments staged in 34.8 KB smem (6 blocks/SM smem-wise)
// deg blocks:  degree + attr scatter-sum, 1024 edges each
// zero blocks: zero accum + denom
__global__ void __launch_bounds__(256, 5)
fat_prologue(const float* __restrict__ x,
             const float* __restrict__ Wl, const float* __restrict__ bl,
             const float* __restrict__ Wr, const float* __restrict__ br,
             const int* __restrict__ ei,
             const float* __restrict__ eattr) {
    extern __shared__ unsigned wfrag[];   // [2][WWORDS]
    int b = (int)(((long)blockIdx.x * FAT_SWZ) % FAT_NB);
    int tid = threadIdx.x;

    if (b < GEMM_NB) {
        int brow = b >> 1;            // 128-row tile
        int h = b & 1;                // column half: cols [h*64, h*64+64)
        // ---- fill W fragment smem (pre-permuted b-frag words) ----
        // per matrix: n_local(64) x p(64); word(n,p) = (W[2p][col], W[2p+1][col])
        // at n*WSTRIDE + q*8 + (r&3)*2 + (r>>2), q=p>>3, r=p&7
        for (int i = tid; i < 4096; i += 256) {
            int n = i & 63, p = i >> 6;
            int col = h * 64 + n;
            int q = p >> 3, r = p & 7;
            int idx = n * WSTRIDE + q * 8 + (r & 3) * 2 + (r >> 2);
            wfrag[idx]          = pack_h2(Wl[(2 * p + 1) * HO + col], Wl[2 * p * HO + col]);
            wfrag[WWORDS + idx] = pack_h2(Wr[(2 * p + 1) * HO + col], Wr[2 * p * HO + col]);
        }
        __syncthreads();

        int w = tid >> 5, lane = tid & 31;
        int grp = lane >> 2, ctg = lane & 3;
        int r0 = brow * 128 + w * 16 + grp;
        int r1 = r0 + 8;

        // A fragments for all 8 k-chunks (fp16), rows r0/r1
        unsigned A0[8], A1[8], A2[8], A3[8];
#pragma unroll
        for (int q = 0; q < 8; q++) {
            if (r0 < NN) {
                float2 v0 = *(const float2*)&x[(long)r0 * INC + q * 16 + 2 * ctg];
                float2 v2 = *(const float2*)&x[(long)r0 * INC + q * 16 + 2 * ctg + 8];
                A0[q] = pack_h2(v0.y, v0.x);
                A2[q] = pack_h2(v2.y, v2.x);
            } else { A0[q] = 0u; A2[q] = 0u; }
            if (r1 < NN) {
                float2 v1 = *(const float2*)&x[(long)r1 * INC + q * 16 + 2 * ctg];
                float2 v3 = *(const float2*)&x[(long)r1 * INC + q * 16 + 2 * ctg + 8];
                A1[q] = pack_h2(v1.y, v1.x);
                A3[q] = pack_h2(v3.y, v3.x);
            } else { A1[q] = 0u; A3[q] = 0u; }
        }

#pragma unroll 1
        for (int m = 0; m < 2; m++) {
            const unsigned* wf = wfrag + m * WWORDS;
            const float* bv = m ? br : bl;
            unsigned* dst = m ? (unsigned*)g_xrh : (unsigned*)g_xlh;
#pragma unroll 1
            for (int t = 0; t < 8; t++) {
                float d0 = 0.f, d1 = 0.f, d2 = 0.f, d3 = 0.f;
                const unsigned* wrow = &wf[(t * 8 + grp) * WSTRIDE + ctg * 2];
#pragma unroll
                for (int q = 0; q < 8; q++) {
                    uint2 bb = *(const uint2*)&wrow[q * 8];
                    asm volatile(
                        "mma.sync.aligned.m16n8k16.row.col.f32.f16.f16.f32 "
                        "{%0,%1,%2,%3}, {%4,%5,%6,%7}, {%8,%9}, {%0,%1,%2,%3};"
                        : "+f"(d0), "+f"(d1), "+f"(d2), "+f"(d3)
                        : "r"(A0[q]), "r"(A1[q]), "r"(A2[q]), "r"(A3[q]),
                          "r"(bb.x), "r"(bb.y));
                }
                float2 bb2 = __ldg((const float2*)&bv[h * 64 + t * 8 + 2 * ctg]);
                d0 += bb2.x; d1 += bb2.y; d2 += bb2.x; d3 += bb2.y;
                int wi = h * 32 + t * 4 + ctg;    // output u32 word = col/2
                if (r0 < NN) dst[(size_t)r0 * 64 + wi] = pack_h2(d1, d0);
                if (r1 < NN) dst[(size_t)r1 * 64 + wi] = pack_h2(d3, d2);
            }
        }
    } else if (b < GEMM_NB + DEG_NB) {
        // ---------------- deg/attr scatter part (1024 edges/block) ---------
        int e0 = (b - GEMM_NB) * 1024 + tid;
#pragma unroll
        for (int it = 0; it < 4; it++) {
            int e = e0 + it * 256;
            if (e < EE) {
                int t = ei[EE + e];
                const float4* a4 = (const float4*)&eattr[(long)e * EDIM];
                float4* dst = &((float4*)g_asum)[(long)t * 4];
#pragma unroll
                for (int q = 0; q < 4; q++) red_add_v4(&dst[q], a4[q]);
                atomicAdd(&g_deg[t], 1.f);
            }
        }
    } else {
        // ---------------- zero part ----------------
        long i = (long)(b - GEMM_NB - DEG_NB) * 256 + tid;
        long stride = (long)ZERO_NB * 256;
        float4* acc = (float4*)g_accum;
        for (long j = i; j < (long)NN * 32; j += stride)
            acc[j] = make_float4(0.f, 0.f, 0.f, 0.f);
        for (long j = i; j < (long)NN * HH; j += stride) g_denom[j] = 0.f;
    }
}

// ---------------- kernel 2: FUSED mma edge projection + edge pass ----------
// Persistent warps grid-stride over 16-edge batches. W_e B-fragments live in
// block-shared smem (4 KB, loaded once). Per batch: 16x mma.m16n8k16 ->
// padded smem fragments -> 16 edges: gather xl/xr fp16, score, exp (no
// max-sub: alpha identical, bounded), scatter denom + exp*xl via RED.v4.
#define SMS 68   // smem row stride in words
__global__ void __launch_bounds__(256, 4)
edge_mma_fused(const int* __restrict__ ei,
               const float* __restrict__ eattr,
               const float* __restrict__ We,
               const float* __restrict__ att) {
    __shared__ unsigned es[8][16 * SMS];
    __shared__ unsigned wsh[16 * 64];   // [t][lane][sel]
    int lane = threadIdx.x & 31;
    int w = threadIdx.x >> 5;
    unsigned* sm = es[w];
    int grp = lane >> 2, ctg = lane & 3;

    // ---- block-shared W_e B-fragments ----
    for (int i = threadIdx.x; i < 512; i += 256) {
        int t = i >> 5, ln = i & 31;
        int g2 = ln >> 2, c2 = ln & 3;
        int col = t * 8 + g2;
        float x0 = __ldg(&We[(2 * c2) * HO + col]);
        float x1 = __ldg(&We[(2 * c2 + 1) * HO + col]);
        float x2 = __ldg(&We[(2 * c2 + 8) * HO + col]);
        float x3 = __ldg(&We[(2 * c2 + 9) * HO + col]);
        wsh[t * 64 + ln * 2]     = pack_h2(x1, x0);
        wsh[t * 64 + ln * 2 + 1] = pack_h2(x3, x2);
    }
    __syncthreads();

    float4 av = __ldg(&((const float4*)att)[lane]);

    // consumer smem word offset for this lane's channel quad
    int pw = (lane >> 1) * 4 + 2 * (lane & 1);

    long warp0 = (long)blockIdx.x * 8 + w;
    long nwarp = (long)gridDim.x * 8;

    for (long batch = warp0; batch < NBATCH; batch += nwarp) {
        long base = batch * 16;
        bool pure = (base + 16 <= EE);

        // prefetched indices for pure batches: lanes 0-15 src, 16-31 tgt
        int idxreg = 0;
        if (pure)
            idxreg = (lane < 16) ? __ldg(&ei[base + lane])
                                 : __ldg(&ei[EE + base + lane - 16]);

        // ---- A fragments: rows base+grp (a0,a2), base+grp+8 (a1,a3) ----
        unsigned a0, a1, a2, a3;
        if (pure) {
            const float* p0 = &eattr[(base + grp) * EDIM];
            float2 lo = *(const float2*)(p0 + 2 * ctg);
            float2 hi = *(const float2*)(p0 + 2 * ctg + 8);
            a0 = pack_h2(lo.y, lo.x);
            a2 = pack_h2(hi.y, hi.x);
            const float* p1 = &eattr[(base + grp + 8) * EDIM];
            float2 lo1 = *(const float2*)(p1 + 2 * ctg);
            float2 hi1 = *(const float2*)(p1 + 2 * ctg + 8);
            a1 = pack_h2(lo1.y, lo1.x);
            a3 = pack_h2(hi1.y, hi1.x);
        } else {
            {
                long row = base + grp;
                const float* p; float inv = 1.f;
                if (row < EE) { p = &eattr[row * EDIM]; }
                else { int n = (int)(row - EE); p = &g_asum[(size_t)n * EDIM];
                       inv = 1.f / fmaxf(g_deg[n], 1.f); }
                float2 lo = *(const float2*)(p + 2 * ctg);
                float2 hi = *(const float2*)(p + 2 * ctg + 8);
                a0 = pack_h2(lo.y * inv, lo.x * inv);
                a2 = pack_h2(hi.y * inv, hi.x * inv);
            }
            {
                long row = base + grp + 8;
                const float* p; float inv = 1.f;
                if (row < EE) { p = &eattr[row * EDIM]; }
                else { int n = (int)(row - EE); p = &g_asum[(size_t)n * EDIM];
                       inv = 1.f / fmaxf(g_deg[n], 1.f); }
                float2 lo = *(const float2*)(p + 2 * ctg);
                float2 hi = *(const float2*)(p + 2 * ctg + 8);
                a1 = pack_h2(lo.y * inv, lo.x * inv);
                a3 = pack_h2(hi.y * inv, hi.x * inv);
            }
        }

        // ---- 16 mma -> smem fragments (B-frag from block smem) ----
        float z = 0.f;
#pragma unroll
        for (int t = 0; t < 16; t++) {
            uint2 bb = *(const uint2*)&wsh[t * 64 + lane * 2];
            float d0, d1, d2, d3;
            asm volatile(
                "mma.sync.aligned.m16n8k16.row.col.f32.f16.f16.f32 "
                "{%0,%1,%2,%3}, {%4,%5,%6,%7}, {%8,%9}, {%10,%10,%10,%10};"
                : "=f"(d0), "=f"(d1), "=f"(d2), "=f"(d3)
                : "r"(a0), "r"(a1), "r"(a2), "r"(a3),
                  "r"(bb.x), "r"(bb.y), "f"(z));
            sm[grp * SMS + t * 4 + ctg]       = pack_h2(d1, d0);
            sm[(grp + 8) * SMS + t * 4 + ctg] = pack_h2(d3, d2);
        }
        __syncwarp();

        // ---- process the 16 edges of this batch ----
#pragma unroll 4
        for (int g16 = 0; g16 < 16; g16++) {
            int s, t;
            if (pure) {
                s = __shfl_sync(0xffffffffu, idxreg, g16);
                t = __shfl_sync(0xffffffffu, idxreg, 16 + g16);
            } else {
                long ew = base + g16;
                if (ew < EE) { s = __ldg(&ei[ew]); t = __ldg(&ei[EE + ew]); }
                else         { s = t = (int)(ew - EE); }
            }

            uint2 xlh = __ldg(&g_xlh[(size_t)s * 32 + lane]);
            uint2 xrh = __ldg(&g_xrh[(size_t)t * 32 + lane]);
            float2 xl01 = __half22float2(*(__half2*)&xlh.x);
            float2 xl23 = __half22float2(*(__half2*)&xlh.y);
            float2 xr01 = __half22float2(*(__half2*)&xrh.x);
            float2 xr23 = __half22float2(*(__half2*)&xrh.y);

            uint2 ev = *(const uint2*)&sm[g16 * SMS + pw];
            float2 e01 = __half22float2(*(__half2*)&ev.x);
            float2 e23 = __half22float2(*(__half2*)&ev.y);

            float m0 = lrelu(xl01.x + xr01.x + e01.x);
            float m1 = lrelu(xl01.y + xr01.y + e01.y);
            float m2 = lrelu(xl23.x + xr23.x + e23.x);
            float m3 = lrelu(xl23.y + xr23.y + e23.y);
            float p = m0 * av.x + m1 * av.y + m2 * av.z + m3 * av.w;
            p += __shfl_xor_sync(0xffffffffu, p, 4);
            p += __shfl_xor_sync(0xffffffffu, p, 2);
            p += __shfl_xor_sync(0xffffffffu, p, 1);

            float ex = __expf(p);

            if ((lane & 7) == 0)
                atomicAdd(&g_denom[(size_t)t * HH + (lane >> 3)], ex);

            red_add_v4(&g_accum[(long)t * 32 + lane],
                       make_float4(ex * xl01.x, ex * xl01.y,
                                   ex * xl23.x, ex * xl23.y));
        }
        __syncwarp();   // protect smem before next batch overwrites
    }
}

// ---------------- kernel 3: finalize (head mean + bias + LeakyReLU) --------
__global__ void finalize_kernel(const float* __restrict__ bias,
                                float* __restrict__ out) {
    int idx = blockIdx.x * blockDim.x + threadIdx.x;
    if (idx >= NN * OUTC) return;
    int n = idx >> 5, c = idx & 31;
    const float* acc = (const float*)g_accum;
    float sum = 0.f;
#pragma unroll
    for (int hh = 0; hh < HH; hh++)
        sum += acc[(size_t)n * HO + hh * OUTC + c] / g_denom[(size_t)n * HH + hh];
    float o = sum * 0.25f + bias[c];
    out[idx] = lrelu(o);
}

// ---------------- launch ---------------------------------------------------
extern "C" void kernel_launch(void* const* d_in, const int* in_sizes, int n_in,
                              void* d_out, int out_size) {
    const float* x     = (const float*)d_in[0];
    const int*   ei    = (const int*)  d_in[1];
    const float* eattr = (const float*)d_in[2];
    const float* Wl    = (const float*)d_in[3];
    const float* bl    = (const float*)d_in[4];
    const float* Wr    = (const float*)d_in[5];
    const float* br    = (const float*)d_in[6];
    const float* We    = (const float*)d_in[7];
    const float* att   = (const float*)d_in[8];
    const float* bias  = (const float*)d_in[9];
    float* out = (float*)d_out;

    // zero the atomic-accumulated self-loop scratch via memset nodes
    void* p_asum = nullptr; cudaGetSymbolAddress(&p_asum, g_asum);
    void* p_deg  = nullptr; cudaGetSymbolAddress(&p_deg,  g_deg);
    cudaMemsetAsync(p_asum, 0, sizeof(float) * (size_t)NN * EDIM);
    cudaMemsetAsync(p_deg,  0, sizeof(float) * (size_t)NN);

    cudaFuncSetAttribute(fat_prologue,
                         cudaFuncAttributeMaxDynamicSharedMemorySize, FAT_SMEM);
    fat_prologue<<<FAT_NB, 256, FAT_SMEM>>>(x, Wl, bl, Wr, br, ei, eattr);
    edge_mma_fused<<<592, 256>>>(ei, eattr, We, att);
    finalize_kernel<<<(NN * OUTC + 255) / 256, 256>>>(bias, out);
}

// round 17
// speedup vs baseline: 1.3410x; 1.0271x over previous
#include <cuda_runtime.h>
#include <cuda_fp16.h>

#define NN   50000
#define EE   800000
#define INC  128
#define OUTC 32
#define HH   4
#define EDIM 16
#define HO   128          // H*OUT
#define ENF  (EE + NN)    // edges + self loops = 850000 (divisible by 16)
#define NBATCH (ENF / 16) // 53125 mma warp batches
#define SLOPE 0.2f

// fat-kernel block partition (striped by a coprime swizzle)
#define GEMM_NB 782       // 2 * ceil(NN/128): 128 rows x 64 cols per block
#define DEG_NB  782       // 1024 edges per block (4 x 256)
#define ZERO_NB 256
#define FAT_NB  (GEMM_NB + DEG_NB + ZERO_NB)   // 1820
#define FAT_SWZ 739       // coprime with 1820

// W fragment smem: 2 matrices x 64 cols x 68-word padded rows
#define WSTRIDE 68
#define WWORDS  (64 * WSTRIDE)           // 4352 words per matrix half
#define FAT_SMEM (2 * WWORDS * 4)        // 34816 bytes

// ---------------- scratch (device globals; no allocation allowed) ----------
__device__ uint2    g_xlh[(size_t)NN * 32];      // x@W_l+b_l fp16 (12.8 MB)
__device__ uint2    g_xrh[(size_t)NN * 32];      // x@W_r+b_r fp16 (12.8 MB)
__device__ float    g_deg[NN];                   // in-degree
__device__ float    g_asum[(size_t)NN * EDIM];   // scatter-sum of edge attrs
__device__ float    g_denom[(size_t)NN * HH];    // softmax denominators
__device__ float4   g_accum[(size_t)NN * OUTC];  // sum exp(s)*x_l[src] (25.6 MB)

// ---------------- helpers --------------------------------------------------
__device__ __forceinline__ float lrelu(float v) { return fmaxf(v, SLOPE * v); }

__device__ __forceinline__ void red_add_v4(float4* addr, float4 v) {
    asm volatile("red.global.add.v4.f32 [%0], {%1,%2,%3,%4};"
                 :: "l"(addr), "f"(v.x), "f"(v.y), "f"(v.z), "f"(v.w)
                 : "memory");
}

// pack two f32 into f16x2: lo -> bits[15:0], hi -> bits[31:16]
__device__ __forceinline__ unsigned pack_h2(float hi, float lo) {
    unsigned r;
    asm("cvt.rn.f16x2.f32 %0, %1, %2;" : "=r"(r) : "f"(hi), "f"(lo));
    return r;
}

// ---------------- kernel 1: FAT prologue (striped block types) --------------
// gemm blocks: x@W_{l,r} via mma.m16n8k16, 128 rows x 64 cols per block,
//              W fragments staged in 34.8 KB smem
// deg blocks:  degree + attr scatter-sum, 1024 edges each
// zero blocks: zero accum + denom
__global__ void __launch_bounds__(256, 5)
fat_prologue(const float* __restrict__ x,
             const float* __restrict__ Wl, const float* __restrict__ bl,
             const float* __restrict__ Wr, const float* __restrict__ br,
             const int* __restrict__ ei,
             const float* __restrict__ eattr) {
    extern __shared__ unsigned wfrag[];   // [2][WWORDS]
    int b = (int)(((long)blockIdx.x * FAT_SWZ) % FAT_NB);
    int tid = threadIdx.x;

    if (b < GEMM_NB) {
        int brow = b >> 1;            // 128-row tile
        int h = b & 1;                // column half: cols [h*64, h*64+64)
        // ---- fill W fragment smem (pre-permuted b-frag words) ----
        for (int i = tid; i < 4096; i += 256) {
            int n = i & 63, p = i >> 6;
            int col = h * 64 + n;
            int q = p >> 3, r = p & 7;
            int idx = n * WSTRIDE + q * 8 + (r & 3) * 2 + (r >> 2);
            wfrag[idx]          = pack_h2(Wl[(2 * p + 1) * HO + col], Wl[2 * p * HO + col]);
            wfrag[WWORDS + idx] = pack_h2(Wr[(2 * p + 1) * HO + col], Wr[2 * p * HO + col]);
        }
        __syncthreads();

        int w = tid >> 5, lane = tid & 31;
        int grp = lane >> 2, ctg = lane & 3;
        int r0 = brow * 128 + w * 16 + grp;
        int r1 = r0 + 8;

        // A fragments for all 8 k-chunks (fp16), rows r0/r1
        unsigned A0[8], A1[8], A2[8], A3[8];
#pragma unroll
        for (int q = 0; q < 8; q++) {
            if (r0 < NN) {
                float2 v0 = *(const float2*)&x[(long)r0 * INC + q * 16 + 2 * ctg];
                float2 v2 = *(const float2*)&x[(long)r0 * INC + q * 16 + 2 * ctg + 8];
                A0[q] = pack_h2(v0.y, v0.x);
                A2[q] = pack_h2(v2.y, v2.x);
            } else { A0[q] = 0u; A2[q] = 0u; }
            if (r1 < NN) {
                float2 v1 = *(const float2*)&x[(long)r1 * INC + q * 16 + 2 * ctg];
                float2 v3 = *(const float2*)&x[(long)r1 * INC + q * 16 + 2 * ctg + 8];
                A1[q] = pack_h2(v1.y, v1.x);
                A3[q] = pack_h2(v3.y, v3.x);
            } else { A1[q] = 0u; A3[q] = 0u; }
        }

#pragma unroll 1
        for (int m = 0; m < 2; m++) {
            const unsigned* wf = wfrag + m * WWORDS;
            const float* bv = m ? br : bl;
            unsigned* dst = m ? (unsigned*)g_xrh : (unsigned*)g_xlh;
#pragma unroll 1
            for (int t = 0; t < 8; t++) {
                float d0 = 0.f, d1 = 0.f, d2 = 0.f, d3 = 0.f;
                const unsigned* wrow = &wf[(t * 8 + grp) * WSTRIDE + ctg * 2];
#pragma unroll
                for (int q = 0; q < 8; q++) {
                    uint2 bb = *(const uint2*)&wrow[q * 8];
                    asm volatile(
                        "mma.sync.aligned.m16n8k16.row.col.f32.f16.f16.f32 "
                        "{%0,%1,%2,%3}, {%4,%5,%6,%7}, {%8,%9}, {%0,%1,%2,%3};"
                        : "+f"(d0), "+f"(d1), "+f"(d2), "+f"(d3)
                        : "r"(A0[q]), "r"(A1[q]), "r"(A2[q]), "r"(A3[q]),
                          "r"(bb.x), "r"(bb.y));
                }
                float2 bb2 = __ldg((const float2*)&bv[h * 64 + t * 8 + 2 * ctg]);
                d0 += bb2.x; d1 += bb2.y; d2 += bb2.x; d3 += bb2.y;
                int wi = h * 32 + t * 4 + ctg;    // output u32 word = col/2
                if (r0 < NN) dst[(size_t)r0 * 64 + wi] = pack_h2(d1, d0);
                if (r1 < NN) dst[(size_t)r1 * 64 + wi] = pack_h2(d3, d2);
            }
        }
    } else if (b < GEMM_NB + DEG_NB) {
        // ---------------- deg/attr scatter part (1024 edges/block) ---------
        int e0 = (b - GEMM_NB) * 1024 + tid;
#pragma unroll
        for (int it = 0; it < 4; it++) {
            int e = e0 + it * 256;
            if (e < EE) {
                int t = ei[EE + e];
                const float4* a4 = (const float4*)&eattr[(long)e * EDIM];
                float4* dst = &((float4*)g_asum)[(long)t * 4];
#pragma unroll
                for (int q = 0; q < 4; q++) red_add_v4(&dst[q], a4[q]);
                atomicAdd(&g_deg[t], 1.f);
            }
        }
    } else {
        // ---------------- zero part ----------------
        long i = (long)(b - GEMM_NB - DEG_NB) * 256 + tid;
        long stride = (long)ZERO_NB * 256;
        float4* acc = (float4*)g_accum;
        for (long j = i; j < (long)NN * 32; j += stride)
            acc[j] = make_float4(0.f, 0.f, 0.f, 0.f);
        for (long j = i; j < (long)NN * HH; j += stride) g_denom[j] = 0.f;
    }
}

// ---------------- kernel 2: FUSED mma edge projection + edge pass ----------
// Persistent warps grid-stride over 16-edge batches. W_e B-fragments live in
// block-shared smem (4 KB, loaded once). Per batch: 16x mma.m16n8k16 ->
// padded smem fragments -> 16 edges: gather xl/xr fp16, score, exp (no
// max-sub: alpha identical, bounded), scatter denom + exp*xl via RED.v4.
// 5 blocks/SM via launch bounds (smem allows 6; regs were the cap at 4).
#define SMS 68   // smem row stride in words
__global__ void __launch_bounds__(256, 5)
edge_mma_fused(const int* __restrict__ ei,
               const float* __restrict__ eattr,
               const float* __restrict__ We,
               const float* __restrict__ att) {
    __shared__ unsigned es[8][16 * SMS];
    __shared__ unsigned wsh[16 * 64];   // [t][lane][sel]
    int lane = threadIdx.x & 31;
    int w = threadIdx.x >> 5;
    unsigned* sm = es[w];
    int grp = lane >> 2, ctg = lane & 3;

    // ---- block-shared W_e B-fragments ----
    for (int i = threadIdx.x; i < 512; i += 256) {
        int t = i >> 5, ln = i & 31;
        int g2 = ln >> 2, c2 = ln & 3;
        int col = t * 8 + g2;
        float x0 = __ldg(&We[(2 * c2) * HO + col]);
        float x1 = __ldg(&We[(2 * c2 + 1) * HO + col]);
        float x2 = __ldg(&We[(2 * c2 + 8) * HO + col]);
        float x3 = __ldg(&We[(2 * c2 + 9) * HO + col]);
        wsh[t * 64 + ln * 2]     = pack_h2(x1, x0);
        wsh[t * 64 + ln * 2 + 1] = pack_h2(x3, x2);
    }
    __syncthreads();

    float4 av = __ldg(&((const float4*)att)[lane]);

    // consumer smem word offset for this lane's channel quad
    int pw = (lane >> 1) * 4 + 2 * (lane & 1);

    long warp0 = (long)blockIdx.x * 8 + w;
    long nwarp = (long)gridDim.x * 8;

    for (long batch = warp0; batch < NBATCH; batch += nwarp) {
        long base = batch * 16;
        bool pure = (base + 16 <= EE);

        // prefetched indices for pure batches: lanes 0-15 src, 16-31 tgt
        int idxreg = 0;
        if (pure)
            idxreg = (lane < 16) ? __ldg(&ei[base + lane])
                                 : __ldg(&ei[EE + base + lane - 16]);

        // ---- A fragments: rows base+grp (a0,a2), base+grp+8 (a1,a3) ----
        unsigned a0, a1, a2, a3;
        if (pure) {
            const float* p0 = &eattr[(base + grp) * EDIM];
            float2 lo = *(const float2*)(p0 + 2 * ctg);
            float2 hi = *(const float2*)(p0 + 2 * ctg + 8);
            a0 = pack_h2(lo.y, lo.x);
            a2 = pack_h2(hi.y, hi.x);
            const float* p1 = &eattr[(base + grp + 8) * EDIM];
            float2 lo1 = *(const float2*)(p1 + 2 * ctg);
            float2 hi1 = *(const float2*)(p1 + 2 * ctg + 8);
            a1 = pack_h2(lo1.y, lo1.x);
            a3 = pack_h2(hi1.y, hi1.x);
        } else {
            {
                long row = base + grp;
                const float* p; float inv = 1.f;
                if (row < EE) { p = &eattr[row * EDIM]; }
                else { int n = (int)(row - EE); p = &g_asum[(size_t)n * EDIM];
                       inv = 1.f / fmaxf(g_deg[n], 1.f); }
                float2 lo = *(const float2*)(p + 2 * ctg);
                float2 hi = *(const float2*)(p + 2 * ctg + 8);
                a0 = pack_h2(lo.y * inv, lo.x * inv);
                a2 = pack_h2(hi.y * inv, hi.x * inv);
            }
            {
                long row = base + grp + 8;
                const float* p; float inv = 1.f;
                if (row < EE) { p = &eattr[row * EDIM]; }
                else { int n = (int)(row - EE); p = &g_asum[(size_t)n * EDIM];
                       inv = 1.f / fmaxf(g_deg[n], 1.f); }
                float2 lo = *(const float2*)(p + 2 * ctg);
                float2 hi = *(const float2*)(p + 2 * ctg + 8);
                a1 = pack_h2(lo.y * inv, lo.x * inv);
                a3 = pack_h2(hi.y * inv, hi.x * inv);
            }
        }

        // ---- 16 mma -> smem fragments (B-frag from block smem) ----
        float z = 0.f;
#pragma unroll
        for (int t = 0; t < 16; t++) {
            uint2 bb = *(const uint2*)&wsh[t * 64 + lane * 2];
            float d0, d1, d2, d3;
            asm volatile(
                "mma.sync.aligned.m16n8k16.row.col.f32.f16.f16.f32 "
                "{%0,%1,%2,%3}, {%4,%5,%6,%7}, {%8,%9}, {%10,%10,%10,%10};"
                : "=f"(d0), "=f"(d1), "=f"(d2), "=f"(d3)
                : "r"(a0), "r"(a1), "r"(a2), "r"(a3),
                  "r"(bb.x), "r"(bb.y), "f"(z));
            sm[grp * SMS + t * 4 + ctg]       = pack_h2(d1, d0);
            sm[(grp + 8) * SMS + t * 4 + ctg] = pack_h2(d3, d2);
        }
        __syncwarp();

        // ---- process the 16 edges of this batch ----
#pragma unroll 4
        for (int g16 = 0; g16 < 16; g16++) {
            int s, t;
            if (pure) {
                s = __shfl_sync(0xffffffffu, idxreg, g16);
                t = __shfl_sync(0xffffffffu, idxreg, 16 + g16);
            } else {
                long ew = base + g16;
                if (ew < EE) { s = __ldg(&ei[ew]); t = __ldg(&ei[EE + ew]); }
                else         { s = t = (int)(ew - EE); }
            }

            uint2 xlh = __ldg(&g_xlh[(size_t)s * 32 + lane]);
            uint2 xrh = __ldg(&g_xrh[(size_t)t * 32 + lane]);
            float2 xl01 = __half22float2(*(__half2*)&xlh.x);
            float2 xl23 = __half22float2(*(__half2*)&xlh.y);
            float2 xr01 = __half22float2(*(__half2*)&xrh.x);
            float2 xr23 = __half22float2(*(__half2*)&xrh.y);

            uint2 ev = *(const uint2*)&sm[g16 * SMS + pw];
            float2 e01 = __half22float2(*(__half2*)&ev.x);
            float2 e23 = __half22float2(*(__half2*)&ev.y);

            float m0 = lrelu(xl01.x + xr01.x + e01.x);
            float m1 = lrelu(xl01.y + xr01.y + e01.y);
            float m2 = lrelu(xl23.x + xr23.x + e23.x);
            float m3 = lrelu(xl23.y + xr23.y + e23.y);
            float p = m0 * av.x + m1 * av.y + m2 * av.z + m3 * av.w;
            p += __shfl_xor_sync(0xffffffffu, p, 4);
            p += __shfl_xor_sync(0xffffffffu, p, 2);
            p += __shfl_xor_sync(0xffffffffu, p, 1);

            float ex = __expf(p);

            if ((lane & 7) == 0)
                atomicAdd(&g_denom[(size_t)t * HH + (lane >> 3)], ex);

            red_add_v4(&g_accum[(long)t * 32 + lane],
                       make_float4(ex * xl01.x, ex * xl01.y,
                                   ex * xl23.x, ex * xl23.y));
        }
        __syncwarp();   // protect smem before next batch overwrites
    }
}

// ---------------- kernel 3: finalize (head mean + bias + LeakyReLU) --------
__global__ void finalize_kernel(const float* __restrict__ bias,
                                float* __restrict__ out) {
    int idx = blockIdx.x * blockDim.x + threadIdx.x;
    if (idx >= NN * OUTC) return;
    int n = idx >> 5, c = idx & 31;
    const float* acc = (const float*)g_accum;
    float sum = 0.f;
#pragma unroll
    for (int hh = 0; hh < HH; hh++)
        sum += acc[(size_t)n * HO + hh * OUTC + c] / g_denom[(size_t)n * HH + hh];
    float o = sum * 0.25f + bias[c];
    out[idx] = lrelu(o);
}

// ---------------- launch ---------------------------------------------------
extern "C" void kernel_launch(void* const* d_in, const int* in_sizes, int n_in,
                              void* d_out, int out_size) {
    const float* x     = (const float*)d_in[0];
    const int*   ei    = (const int*)  d_in[1];
    const float* eattr = (const float*)d_in[2];
    const float* Wl    = (const float*)d_in[3];
    const float* bl    = (const float*)d_in[4];
    const float* Wr    = (const float*)d_in[5];
    const float* br    = (const float*)d_in[6];
    const float* We    = (const float*)d_in[7];
    const float* att   = (const float*)d_in[8];
    const float* bias  = (const float*)d_in[9];
    float* out = (float*)d_out;

    // zero the atomic-accumulated self-loop scratch via memset nodes
    void* p_asum = nullptr; cudaGetSymbolAddress(&p_asum, g_asum);
    void* p_deg  = nullptr; cudaGetSymbolAddress(&p_deg,  g_deg);
    cudaMemsetAsync(p_asum, 0, sizeof(float) * (size_t)NN * EDIM);
    cudaMemsetAsync(p_deg,  0, sizeof(float) * (size_t)NN);

    cudaFuncSetAttribute(fat_prologue,
                         cudaFuncAttributeMaxDynamicSharedMemorySize, FAT_SMEM);
    fat_prologue<<<FAT_NB, 256, FAT_SMEM>>>(x, Wl, bl, Wr, br, ei, eattr);
    edge_mma_fused<<<740, 256>>>(ei, eattr, We, att);
    finalize_kernel<<<(NN * OUTC + 255) / 256, 256>>>(bias, out);
}